// round 3
// baseline (speedup 1.0000x reference)
#include <cuda_runtime.h>

#define HH 2048
#define WW 2048
#define HWT (HH*WW)
#define RD 7
#define RG 60
#define KSEL 4195u          /* (H*W)//1000 + 1 : rank of threshold (1-based from top) */
#define OMEGA 0.95f
#define EPSG 1e-4f

// ---------------- scratch (device globals; no allocation) ----------------
__device__ float    g_dch[HWT];          // horizontal-min intermediate
__device__ float    g_dc[HWT];           // dark channel
__device__ float    g_hsum[10*HWT];      // 10 horizontally box-summed planes (160MB)
__device__ unsigned g_hist1[65536];
__device__ unsigned g_hist2[65536];
__device__ unsigned g_selB;
__device__ unsigned g_selRank;
__device__ float    g_thres;
__device__ unsigned g_cnt;
__device__ float    g_sumr, g_sumg, g_sumb;
__device__ float    g_avg, g_invavg;

// ---------------- init: zero histograms / accumulators ----------------
__global__ void k_init() {
    int i = blockIdx.x * blockDim.x + threadIdx.x;
    if (i < 65536) { g_hist1[i] = 0u; g_hist2[i] = 0u; }
    if (i == 0) {
        g_cnt = 0u; g_sumr = 0.f; g_sumg = 0.f; g_sumb = 0.f;
        g_selB = 0u; g_selRank = 0u; g_thres = 0.f;
    }
}

// ---------------- channel-min + horizontal min (r=7) ----------------
__global__ void __launch_bounds__(256) k_cmin_hmin(const float* __restrict__ x) {
    __shared__ float s[256 + 2*RD];
    int row = blockIdx.y;
    int x0  = blockIdx.x * 256;
    int t   = threadIdx.x;
    for (int i = t; i < 256 + 2*RD; i += 256) {
        int xx = x0 - RD + i;
        float v = 1e30f;
        if (xx >= 0 && xx < WW) {
            float r = x[0*HWT + row*WW + xx];
            float g = x[1*HWT + row*WW + xx];
            float b = x[2*HWT + row*WW + xx];
            v = fminf(r, fminf(g, b));
        }
        s[i] = v;
    }
    __syncthreads();
    float m = s[t];
#pragma unroll
    for (int j = 1; j <= 2*RD; j++) m = fminf(m, s[t + j]);
    g_dch[row*WW + x0 + t] = m;
}

// ---------------- vertical min (r=7) ----------------
__global__ void __launch_bounds__(256) k_vmin() {
    __shared__ float s[16 + 2*RD][256];
    int xx = blockIdx.x * 256 + threadIdx.x;
    int y0 = blockIdx.y * 16;
    for (int r = 0; r < 16 + 2*RD; r++) {
        int yy = y0 - RD + r;
        s[r][threadIdx.x] = (yy >= 0 && yy < HH) ? g_dch[yy*WW + xx] : 1e30f;
    }
    __syncthreads();
    for (int k = 0; k < 16; k++) {
        float m = s[k][threadIdx.x];
#pragma unroll
        for (int j = 1; j <= 2*RD; j++) m = fminf(m, s[k + j][threadIdx.x]);
        g_dc[(y0 + k)*WW + xx] = m;
    }
}

// ---------------- histogram pass 1 (top 16 bits) with warp run-length dedup ----------------
__global__ void k_hist1() {
    int tid = blockIdx.x * blockDim.x + threadIdx.x;
    int stride = gridDim.x * blockDim.x;
    int lane = threadIdx.x & 31;
    for (int i = tid; i < HWT; i += stride) {
        unsigned key = __float_as_uint(g_dc[i]) >> 16;
        unsigned prev = __shfl_up_sync(0xffffffffu, key, 1);
        bool leader = (lane == 0) || (key != prev);
        unsigned bal = __ballot_sync(0xffffffffu, leader);
        if (leader) {
            unsigned above = (lane == 31) ? 0u : (bal >> (lane + 1));
            int run = above ? __ffs((int)above) : (32 - lane);
            atomicAdd(&g_hist1[key], (unsigned)run);
        }
    }
}

// ---------------- find bin containing the KSEL-th largest ----------------
__global__ void k_scan1() {
    __shared__ unsigned part[256];
    int t = threadIdx.x;
    int hi = 65535 - 256 * t;
    unsigned sum = 0;
    for (int j = 0; j < 256; j++) sum += g_hist1[hi - j];
    part[t] = sum;
    __syncthreads();
    if (t == 0) {
        unsigned cum = 0; int sel = 0;
        for (int i = 0; i < 256; i++) {
            if (cum + part[i] >= KSEL) { sel = i; break; }
            cum += part[i];
        }
        int hb = 65535 - 256 * sel;
        for (int j = 0; j < 256; j++) {
            unsigned h = g_hist1[hb - j];
            if (cum + h >= KSEL) {
                g_selB = (unsigned)(hb - j);
                g_selRank = KSEL - cum;
                break;
            }
            cum += h;
        }
    }
}

// ---------------- histogram pass 2 (low 16 bits within selected bin) ----------------
__global__ void k_hist2() {
    unsigned B = g_selB;
    int tid = blockIdx.x * blockDim.x + threadIdx.x;
    int stride = gridDim.x * blockDim.x;
    for (int i = tid; i < HWT; i += stride) {
        unsigned bits = __float_as_uint(g_dc[i]);
        if ((bits >> 16) == B) atomicAdd(&g_hist2[bits & 0xFFFFu], 1u);
    }
}

// ---------------- find exact threshold value ----------------
__global__ void k_scan2() {
    __shared__ unsigned part[256];
    unsigned K = g_selRank;
    int t = threadIdx.x;
    int hi = 65535 - 256 * t;
    unsigned sum = 0;
    for (int j = 0; j < 256; j++) sum += g_hist2[hi - j];
    part[t] = sum;
    __syncthreads();
    if (t == 0) {
        unsigned cum = 0; int sel = 0;
        for (int i = 0; i < 256; i++) {
            if (cum + part[i] >= K) { sel = i; break; }
            cum += part[i];
        }
        int hb = 65535 - 256 * sel;
        for (int j = 0; j < 256; j++) {
            unsigned h = g_hist2[hb - j];
            if (cum + h >= K) {
                g_thres = __uint_as_float((g_selB << 16) | (unsigned)(hb - j));
                break;
            }
            cum += h;
        }
    }
}

// ---------------- masked sums for atmospheric light ----------------
__global__ void k_mask(const float* __restrict__ x) {
    float th = g_thres;
    int tid = blockIdx.x * blockDim.x + threadIdx.x;
    int stride = gridDim.x * blockDim.x;
    unsigned cnt = 0; float sr = 0.f, sg = 0.f, sb = 0.f;
    for (int i = tid; i < HWT; i += stride) {
        if (g_dc[i] >= th) {
            cnt++;
            sr += x[i];
            sg += x[HWT + i];
            sb += x[2*HWT + i];
        }
    }
#pragma unroll
    for (int o = 16; o > 0; o >>= 1) {
        cnt += __shfl_down_sync(0xffffffffu, cnt, o);
        sr  += __shfl_down_sync(0xffffffffu, sr,  o);
        sg  += __shfl_down_sync(0xffffffffu, sg,  o);
        sb  += __shfl_down_sync(0xffffffffu, sb,  o);
    }
    if ((threadIdx.x & 31) == 0) {
        atomicAdd(&g_cnt, cnt);
        atomicAdd(&g_sumr, sr);
        atomicAdd(&g_sumg, sg);
        atomicAdd(&g_sumb, sb);
    }
}

__global__ void k_avg() {
    float c = (float)g_cnt;
    float avg = (0.299f * g_sumr + 0.587f * g_sumg + 0.114f * g_sumb) / c;
    g_avg = avg;
    g_invavg = 1.0f / avg;
}

// ---------------- guided filter: horizontal box sums of 10 planes ----------------
// one block per row; shared-memory prefix scan; windowed diff with truncated windows
__global__ void __launch_bounds__(256) k_hpass(const float* __restrict__ x) {
    __shared__ float sx0[WW], sx1[WW], sx2[WW], st[WW], sp[WW];
    __shared__ float wpart[8];
    int row = blockIdx.x, t = threadIdx.x;
    float inva = g_invavg;
#pragma unroll
    for (int j = 0; j < 8; j++) {
        int xx = t + j * 256;
        sx0[xx] = x[row*WW + xx];
        sx1[xx] = x[HWT + row*WW + xx];
        sx2[xx] = x[2*HWT + row*WW + xx];
        st[xx]  = 1.0f - OMEGA * g_dc[row*WW + xx] * inva;
    }
    __syncthreads();
    int lane = t & 31, wid = t >> 5;
#pragma unroll
    for (int pl = 0; pl < 10; pl++) {
        float c[8];
        int base = t * 8;
#pragma unroll
        for (int j = 0; j < 8; j++) {
            int xx = base + j;
            float v;
            switch (pl) {
                case 0: v = st[xx]; break;
                case 1: v = sx0[xx]; break;
                case 2: v = sx1[xx]; break;
                case 3: v = sx2[xx]; break;
                case 4: v = st[xx] * sx0[xx]; break;
                case 5: v = st[xx] * sx1[xx]; break;
                case 6: v = st[xx] * sx2[xx]; break;
                case 7: v = sx0[xx] * sx0[xx]; break;
                case 8: v = sx1[xx] * sx1[xx]; break;
                default: v = sx2[xx] * sx2[xx]; break;
            }
            c[j] = v;
        }
#pragma unroll
        for (int j = 1; j < 8; j++) c[j] += c[j - 1];
        float tot = c[7];
        float v = tot;
#pragma unroll
        for (int o = 1; o < 32; o <<= 1) {
            float n = __shfl_up_sync(0xffffffffu, v, o);
            if (lane >= o) v += n;
        }
        if (lane == 31) wpart[wid] = v;
        __syncthreads();
        float off = v - tot;                 // exclusive within warp
        for (int w = 0; w < wid; w++) off += wpart[w];
#pragma unroll
        for (int j = 0; j < 8; j++) sp[base + j] = c[j] + off;
        __syncthreads();
        float* dst = g_hsum + pl * HWT + row * WW;
#pragma unroll
        for (int j = 0; j < 8; j++) {
            int xx = t + j * 256;
            int hi = xx + RG; if (hi > WW - 1) hi = WW - 1;
            float sv = sp[hi];
            int lo = xx - RG - 1;
            if (lo >= 0) sv -= sp[lo];
            dst[xx] = sv;
        }
        __syncthreads();
    }
}

// ---------------- vertical rolling box sums + full epilogue ----------------
__global__ void __launch_bounds__(128) k_vfinal(const float* __restrict__ x,
                                                float* __restrict__ out) {
    const int S = 128;
    int xx = blockIdx.x * 128 + threadIdx.x;
    int y0 = blockIdx.y * S;
    float s[10];
#pragma unroll
    for (int p = 0; p < 10; p++) s[p] = 0.f;
    int ylo = y0 - RG; if (ylo < 0) ylo = 0;
    int yhi = y0 + RG; if (yhi > HH - 1) yhi = HH - 1;
    for (int yy = ylo; yy <= yhi; yy++) {
        const float* __restrict__ hp = g_hsum + yy * WW + xx;
#pragma unroll
        for (int p = 0; p < 10; p++) s[p] += hp[p * HWT];
    }
    int nx = min(xx + RG, WW - 1) - max(xx - RG, 0) + 1;
    float avg = g_avg;
    for (int k = 0; k < S; k++) {
        int y = y0 + k;
        if (k > 0) {
            int ya = y + RG;
            if (ya < HH) {
                const float* __restrict__ hp = g_hsum + ya * WW + xx;
#pragma unroll
                for (int p = 0; p < 10; p++) s[p] += hp[p * HWT];
            }
            int yr = y - RG - 1;
            if (yr >= 0) {
                const float* __restrict__ hp = g_hsum + yr * WW + xx;
#pragma unroll
                for (int p = 0; p < 10; p++) s[p] -= hp[p * HWT];
            }
        }
        int ny = min(y + RG, HH - 1) - max(y - RG, 0) + 1;
        float invN = __fdividef(1.0f, (float)(nx * ny));
        float mp = s[0] * invN;
#pragma unroll
        for (int ch = 0; ch < 3; ch++) {
            float mi  = s[1 + ch] * invN;
            float mpi = s[4 + ch] * invN;
            float mii = s[7 + ch] * invN;
            float cip = mpi - mp * mi;
            float cii = mii - mi * mi;
            float a = __fdividef(cip, cii + EPSG);
            float b = mp - a * mi;
            float xi = x[ch * HWT + y * WW + xx];
            float rt = a * xi + b;
            rt = fminf(fmaxf(rt, 0.0f), 1.0f);
            rt = fmaxf(rt, 0.1f);
            float yv = __fdividef(xi - avg, rt) + avg;
            yv = fminf(fmaxf(yv, 0.0f), 1.0f);
            out[ch * HWT + y * WW + xx] = yv;
        }
    }
}

// ---------------- launch ----------------
extern "C" void kernel_launch(void* const* d_in, const int* in_sizes, int n_in,
                              void* d_out, int out_size) {
    const float* x = (const float*)d_in[0];
    float* out = (float*)d_out;

    k_init<<<256, 256>>>();
    k_cmin_hmin<<<dim3(8, 2048), 256>>>(x);
    k_vmin<<<dim3(8, 128), 256>>>();
    k_hist1<<<1024, 256>>>();
    k_scan1<<<1, 256>>>();
    k_hist2<<<1024, 256>>>();
    k_scan2<<<1, 256>>>();
    k_mask<<<1024, 256>>>(x);
    k_avg<<<1, 1>>>();
    k_hpass<<<2048, 256>>>(x);
    k_vfinal<<<dim3(16, 16), 128>>>(x, out);
}